// round 16
// baseline (speedup 1.0000x reference)
#include <cuda_runtime.h>
#include <cuda_fp16.h>
#include <cstdint>
#include <cstddef>

#define T_STEPS 512
#define BATCH   32
#define HID     1024
#define GDIM    4096
#define MROWS   16384          // T*B
#define YW      2048           // 2*H

typedef unsigned long long ull;

// ---------------- device scratch (no runtime allocation) ----------------
__device__ float g_gx[134217728];          // [2][MROWS][GDIM]  512 MB
__device__ __half g_hH[2][2][32 * 1024];   // [dir][parity][b*1024+k] fp16
__device__ unsigned g_bar_cnt[2]   = {0, 0};
__device__ unsigned g_bar_phase[2] = {0, 0};
__device__ unsigned g_flag[2][64];         // per-CTA step flags
__device__ __half g_wih[36700160];         // w_ih fp16 (all 6)
__device__ __half g_act[33554432];         // activations fp16 [16384 x 2048]
// W_hh baked per-thread fragment streams (8 warps = 4 mi x 2 kh):
// [ld 6][cb 64][wr 8][kt 32][lane 32] x 16B (one fp16 A-fragment)
__device__ uint4 g_wrec[3145728];          // 48 MB

// ---------------- helpers ----------------
__device__ __forceinline__ uint32_t smem_u32(const void* p) {
    uint32_t a;
    asm("{ .reg .u64 t; cvta.to.shared.u64 t, %1; cvt.u32.u64 %0, t; }" : "=r"(a) : "l"(p));
    return a;
}
#define SW128(o) ((o) ^ (((o) >> 3) & 0x70))

#define MMA_F16(d, a, b0v, b1v)                                               \
    asm volatile("mma.sync.aligned.m16n8k16.row.col.f32.f16.f16.f32 "         \
        "{%0,%1,%2,%3}, {%4,%5,%6,%7}, {%8,%9}, {%0,%1,%2,%3};"               \
        : "+f"((d)[0]), "+f"((d)[1]), "+f"((d)[2]), "+f"((d)[3])              \
        : "r"((a)[0]), "r"((a)[1]), "r"((a)[2]), "r"((a)[3]),                 \
          "r"(b0v), "r"(b1v))

#define LDSM4(r, addr)                                                        \
    asm volatile("ldmatrix.sync.aligned.m8n8.x4.shared.b16 "                  \
        "{%0,%1,%2,%3}, [%4];"                                                \
        : "=r"((r)[0]), "=r"((r)[1]), "=r"((r)[2]), "=r"((r)[3])              \
        : "r"(addr))

#define CP_ASYNC16(smaddr, gaddr)                                             \
    asm volatile("cp.async.cg.shared.global [%0], [%1], 16;"                  \
        :: "r"(smaddr), "l"(gaddr) : "memory")
#define CP_COMMIT() asm volatile("cp.async.commit_group;" ::: "memory")
#define CP_WAIT0()  asm volatile("cp.async.wait_group 0;" ::: "memory")
#define CP_WAIT1()  asm volatile("cp.async.wait_group 1;" ::: "memory")

__device__ __forceinline__ float hsig(float v)  { return fminf(fmaxf(fmaf(v, 0.2f, 0.5f), 0.0f), 1.0f); }
__device__ __forceinline__ float clip1(float v) { return fminf(fmaxf(v, -1.0f), 1.0f); }

// legacy counter barrier (used twice per launch: init + final; keeps phase parity even)
__device__ __forceinline__ void grid_barrier(int dir, unsigned& sense) {
    __syncthreads();
    sense ^= 1u;
    if (threadIdx.x == 0) {
        unsigned prev;
        asm volatile("atom.add.acq_rel.gpu.u32 %0, [%1], 1;"
                     : "=r"(prev) : "l"(&g_bar_cnt[dir]) : "memory");
        if (prev == 63u) {
            asm volatile("st.relaxed.gpu.u32 [%0], %1;"
                         :: "l"(&g_bar_cnt[dir]), "r"(0u) : "memory");
            unsigned dummy;
            asm volatile("atom.exch.release.gpu.b32 %0, [%1], %2;"
                         : "=r"(dummy) : "l"(&g_bar_phase[dir]), "r"(sense) : "memory");
        } else {
            unsigned ph;
            do {
                __nanosleep(64);
                asm volatile("ld.acquire.gpu.u32 %0, [%1];"
                             : "=r"(ph) : "l"(&g_bar_phase[dir]) : "memory");
            } while (ph != sense);
        }
    }
    __syncthreads();
}

// contention-free flag barrier: own-flag release store + 32-lane acquire polling
__device__ __forceinline__ void flag_barrier(int dir, int cb, unsigned target) {
    __syncthreads();
    const int tid = threadIdx.x;
    if (tid == 0) {
        asm volatile("st.release.gpu.u32 [%0], %1;"
                     :: "l"(&g_flag[dir][cb]), "r"(target) : "memory");
    }
    if (tid < 32) {
        const unsigned* f1p = &g_flag[dir][tid];
        const unsigned* f2p = &g_flag[dir][tid + 32];
        for (;;) {
            unsigned f1, f2;
            asm volatile("ld.acquire.gpu.u32 %0, [%1];" : "=r"(f1) : "l"(f1p) : "memory");
            asm volatile("ld.acquire.gpu.u32 %0, [%1];" : "=r"(f2) : "l"(f2p) : "memory");
            bool ok = (f1 >= target) && (f2 >= target);
            if (__all_sync(0xffffffffu, ok)) break;
            __nanosleep(32);
        }
    }
    __syncthreads();
}

// ---------------- W_hh prep: bake fp16 fragment streams ----------------
// Rec warp layout: wr(0..7) -> mi = wr>>1 (gate tile), kh = wr&1 (K half).
struct W6 { const float* w[6]; };

__global__ void __launch_bounds__(256)
wrec_prep(W6 p, uint4* __restrict__ out)
{
    const int cb = blockIdx.x;
    const int ld = blockIdx.y;
    const float* __restrict__ w = p.w[ld];
    for (int it = 0; it < 32; it++) {
        int v    = it * 256 + threadIdx.x;   // 0..8191 = 8 wr x 32 kt x 32 lanes
        int wr   = v >> 10;
        int kt   = (v >> 5) & 31;
        int lane = v & 31;
        int mi = wr >> 1, kh = wr & 1;
        unsigned short fr[8];
#pragma unroll
        for (int j = 0; j < 4; j++) {
            int r  = (lane >> 2) + (j & 1) * 8;
            int kc = (lane & 3) * 2 + (j >> 1) * 8;
            int row = mi * HID + cb * 16 + r;
            int k   = kh * 512 + kt * 16 + kc;
#pragma unroll
            for (int e = 0; e < 2; e++) {
                __half h = __float2half_rn(w[(size_t)row * HID + k + e]);
                fr[j * 2 + e] = *(unsigned short*)&h;
            }
        }
        out[(((size_t)(ld * 64 + cb) * 8 + wr) * 32 + kt) * 32 + lane] = *(uint4*)fr;
    }
}

// ---------------- w_ih fp16 conversion (all 6 in one launch) ----------------
__global__ void __launch_bounds__(256)
wih_split(W6 p, __half* __restrict__ out_base)
{
    const int ld = blockIdx.y;
    const size_t woff = (ld == 0) ? 0u :
                        (ld == 1) ? 1310720u :
                        (size_t)2621440u + (size_t)(ld - 2) * 8388608u;
    const int n4 = (ld < 2) ? 327680 : 2097152;
    int i = blockIdx.x * 256 + threadIdx.x;
    if (i >= n4) return;
    float4 v = ((const float4*)p.w[ld])[i];
    __half2* O = (__half2*)(out_base + woff) + i * 2;
    O[0] = __half2(__float2half_rn(v.x), __float2half_rn(v.y));
    O[1] = __half2(__float2half_rn(v.z), __float2half_rn(v.w));
}

// ---------------- tensor-core input-projection GEMM (fp16, 2-stage cp.async) ----------------
#define SMO_A 0
#define SMO_B 16384
#define STAGE_BYTES 32768
#define SMO_BIAS 65536
#define GEMM_SMEM (65536 + 512)

__global__ void __launch_bounds__(256)
gemm_mma(int K, const float* __restrict__ Afp,
         const __half* __restrict__ Ah,
         const __half* __restrict__ WF, const __half* __restrict__ WR,
         const float* __restrict__ bf1, const float* __restrict__ bf2,
         const float* __restrict__ br1, const float* __restrict__ br2,
         float* __restrict__ G)
{
    extern __shared__ char sm[];
    const uint32_t smb = smem_u32(sm);
    const int tid  = threadIdx.x;
    const int wid  = tid >> 5;
    const int lane = tid & 31;
    const int z    = blockIdx.z;

    const __half* __restrict__ W  = z ? WR  : WF;
    const float* __restrict__ b1 = z ? br1 : bf1;
    const float* __restrict__ b2 = z ? br2 : bf2;
    float* __restrict__ Gz = G + (size_t)z * MROWS * GDIM;

    const int n0 = blockIdx.x * 128;
    const int m0 = blockIdx.y * 128;
    const int wm = (wid >> 2) * 64;
    const int wn = (wid & 3) * 32;

    {
        float* bias = (float*)(sm + SMO_BIAS);
        if (tid < 128) bias[tid] = b1[n0 + tid] + b2[n0 + tid];
    }

    float acc[4][4][4];
#pragma unroll
    for (int mi = 0; mi < 4; mi++)
#pragma unroll
        for (int ni = 0; ni < 4; ni++)
#pragma unroll
            for (int e = 0; e < 4; e++) acc[mi][ni][e] = 0.0f;

    const int nk = K >> 6;

    int srow[4], scol[4];
    uint32_t soff[4];
#pragma unroll
    for (int i = 0; i < 4; i++) {
        int v = tid + i * 256;
        srow[i] = v >> 3;
        scol[i] = (v & 7) * 8;
        soff[i] = SW128((uint32_t)(srow[i] * 128 + (v & 7) * 16));
    }

#define GEMM_MMA_CHUNK(SB)                                                    \
    {                                                                         \
        _Pragma("unroll")                                                     \
        for (int ks = 0; ks < 4; ks++) {                                      \
            uint32_t ah[4][4], bh[2][4];                                      \
            _Pragma("unroll")                                                 \
            for (int mi = 0; mi < 4; mi++) {                                  \
                uint32_t off = SW128((uint32_t)(                              \
                    (wm + mi * 16 + (lane & 15)) * 128 + ks * 32 + (lane >> 4) * 16)); \
                LDSM4(ah[mi], smb + (SB) + SMO_A + off);                      \
            }                                                                 \
            _Pragma("unroll")                                                 \
            for (int p = 0; p < 2; p++) {                                     \
                int q  = lane >> 3;                                           \
                int nf = q >> 1, kl = q & 1;                                  \
                uint32_t off = SW128((uint32_t)(                              \
                    (wn + p * 16 + nf * 8 + (lane & 7)) * 128 + ks * 32 + kl * 16)); \
                LDSM4(bh[p], smb + (SB) + SMO_B + off);                       \
            }                                                                 \
            _Pragma("unroll")                                                 \
            for (int mi = 0; mi < 4; mi++) {                                  \
                _Pragma("unroll")                                             \
                for (int ni = 0; ni < 4; ni++) {                              \
                    const int p = ni >> 1, s = (ni & 1) * 2;                  \
                    MMA_F16(acc[mi][ni], ah[mi], bh[p][s], bh[p][s + 1]);     \
                }                                                             \
            }                                                                 \
        }                                                                     \
    }

    if (Afp) {
        for (int ch = 0; ch < nk; ch++) {
            const int kc = ch * 64;
            __syncthreads();
#pragma unroll
            for (int i = 0; i < 4; i++) {
                size_t ga = (size_t)(m0 + srow[i]) * K + kc + scol[i];
                size_t gb = (size_t)(n0 + srow[i]) * K + kc + scol[i];
                float4 f0 = *(const float4*)(Afp + ga);
                float4 f1 = *(const float4*)(Afp + ga + 4);
                float fv[8] = {f0.x, f0.y, f0.z, f0.w, f1.x, f1.y, f1.z, f1.w};
                unsigned short hh[8];
#pragma unroll
                for (int j = 0; j < 8; j++) {
                    __half h = __float2half_rn(fv[j]);
                    hh[j] = *(unsigned short*)&h;
                }
                *(uint4*)(sm + SMO_A + soff[i]) = *(uint4*)hh;
                *(uint4*)(sm + SMO_B + soff[i]) = *(const uint4*)(W + gb);
            }
            __syncthreads();
            GEMM_MMA_CHUNK(0u)
        }
    } else {
#define GEMM_STAGE(CH, PB)                                                    \
        {                                                                     \
            const int kc_ = (CH) * 64;                                        \
            const uint32_t sb_ = (uint32_t)(PB) * STAGE_BYTES;                \
            _Pragma("unroll")                                                 \
            for (int i = 0; i < 4; i++) {                                     \
                size_t ga = (size_t)(m0 + srow[i]) * K + kc_ + scol[i];       \
                size_t gb = (size_t)(n0 + srow[i]) * K + kc_ + scol[i];       \
                CP_ASYNC16(smb + sb_ + SMO_A + soff[i], Ah + ga);             \
                CP_ASYNC16(smb + sb_ + SMO_B + soff[i], W + gb);              \
            }                                                                 \
        }
        GEMM_STAGE(0, 0)
        CP_COMMIT();
        for (int ch = 0; ch < nk; ch++) {
            if (ch + 1 < nk) {
                GEMM_STAGE(ch + 1, (ch + 1) & 1)
                CP_COMMIT();
                CP_WAIT1();
            } else {
                CP_WAIT0();
            }
            __syncthreads();
            const uint32_t sb = (uint32_t)(ch & 1) * STAGE_BYTES;
            GEMM_MMA_CHUNK(sb)
            __syncthreads();
        }
#undef GEMM_STAGE
    }

    const float* bias = (const float*)(sm + SMO_BIAS);
    const int qr = lane >> 2;
    const int qc = (lane & 3) * 2;
#pragma unroll
    for (int mi = 0; mi < 4; mi++) {
#pragma unroll
        for (int ni = 0; ni < 4; ni++) {
            int col = wn + ni * 8 + qc;
            float bx = bias[col], by = bias[col + 1];
            size_t base0 = (size_t)(m0 + wm + mi * 16 + qr) * GDIM + n0 + col;
            size_t base1 = base0 + (size_t)8 * GDIM;
            *(float2*)&Gz[base0] = make_float2(acc[mi][ni][0] + bx, acc[mi][ni][1] + by);
            *(float2*)&Gz[base1] = make_float2(acc[mi][ni][2] + bx, acc[mi][ni][3] + by);
        }
    }
}

// ---------------- persistent fp16 tensor-core recurrence (flag barrier) ----------------
// 128 CTAs x 256 threads. dir = blockIdx.x>>6; CTA owns 16 units (64 gate rows).
// Warp wrp: mi = wrp>>1 (gate tile), kh = wrp&1 (K half). Warp = m16 x n32 x K512.
// fp16 single plane; W depth-8 register ring; gx staged coalesced into smem.
#define RSM_H  0
#define RSM_G  65536
#define RSM_GX (65536 + 2*64*33*4)              // 82432
#define REC_SMEM (82432 + 32*68*4)              // 91136 B

__global__ void __launch_bounds__(256)
rec_kernel(const uint4* __restrict__ wrec,
           const float* __restrict__ h0, const float* __restrict__ c0,
           int layer, const float* __restrict__ gx,
           float* __restrict__ yfp, __half* __restrict__ yh)
{
    extern __shared__ char sm[];
    const uint32_t smb = smem_u32(sm);
    float* G0 = (float*)(sm + RSM_G);          // [64][33] K-half 0
    float* G1 = G0 + 64 * 33;                  // [64][33] K-half 1
    float* gxbuf = (float*)(sm + RSM_GX);      // [32][68]

    const int tid  = threadIdx.x;
    const int lane = tid & 31;
    const int wrp  = tid >> 5;
    const int mi   = wrp >> 1;
    const int kh   = wrp & 1;
    const int dir  = blockIdx.x >> 6;
    const int cb   = blockIdx.x & 63;
    const int ld   = layer * 2 + dir;
    const float* __restrict__ gxd = gx + (size_t)dir * MROWS * GDIM;
    const uint4* __restrict__ wfrag =
        wrec + ((size_t)(ld * 64 + cb) * 8 + wrp) * 1024 + lane;

    // reset own flag (made visible to all by the initial counter barrier)
    if (tid == 0) {
        asm volatile("st.relaxed.gpu.u32 [%0], %1;"
                     :: "l"(&g_flag[dir][cb]), "r"(0u) : "memory");
    }

    // c-state: 2 (unit,batch) pairs per thread
    float cst[2];
    int uu[2], bb[2];
#pragma unroll
    for (int q = 0; q < 2; q++) {
        int p = q * 256 + tid;
        uu[q] = p >> 5;
        bb[q] = p & 31;
        size_t sidx = (size_t)(2 * layer + dir) * BATCH * HID +
                      (size_t)bb[q] * HID + cb * 16 + uu[q];
        cst[q] = c0[sidx];
        g_hH[dir][0][bb[q] * 1024 + cb * 16 + uu[q]] = __float2half_rn(h0[sidx]);
    }

    // preload W ring (kt=0..7)
    uint4 pw[8];
#pragma unroll
    for (int s = 0; s < 8; s++) pw[s] = wfrag[s * 32];

    unsigned sense = 0;
    grid_barrier(dir, sense);   // publish initial h + flag reset

    // gx staging coords: 2 float4 per thread
    int gxb[2], gxg[2], gxu[2];
#pragma unroll
    for (int j = 0; j < 2; j++) {
        int v4 = tid + j * 256;
        gxb[j] = v4 >> 4;
        gxg[j] = (v4 & 15) >> 2;
        gxu[j] = (v4 & 3) * 4;
    }

    // ldsm B address components (batches 0-15 and 16-31)
    const int qq = lane >> 3, nf = qq >> 1, kl = qq & 1;
    const uint32_t brow0 = (uint32_t)((nf * 8 + (lane & 7)) * 128 + kl * 16);
    const uint32_t brow1 = brow0 + 16 * 128;

    for (int t = 0; t < T_STEPS; t++) {
        const int par = t & 1;
        const int te  = dir ? (T_STEPS - 1 - t) : t;

        // stage gx (coalesced float4) + h (64KB fp16) into smem
        {
            const float* gxs = gxd + (size_t)te * BATCH * GDIM;
#pragma unroll
            for (int j = 0; j < 2; j++) {
                float4 d = *(const float4*)(gxs + (size_t)gxb[j] * GDIM +
                                            gxg[j] * HID + cb * 16 + gxu[j]);
                *(float4*)(gxbuf + gxb[j] * 68 + gxg[j] * 16 + gxu[j]) = d;
            }
            const uint4* hsrc = (const uint4*)&g_hH[dir][par][0];
#pragma unroll
            for (int i = 0; i < 16; i++) {
                int v = tid + i * 256;
                int b = v >> 7;
                int kx = v & 127;
                int blk = kx >> 3, cq = kx & 7;
                uint4 d = __ldcg(hsrc + v);
                *(uint4*)(sm + blk * 4096 + SW128((uint32_t)(b * 128 + cq * 16))) = d;
            }
        }
        __syncthreads();   // h+gx staged; guards G/gx buffer reuse from prev step

        float acc[4][4];
#pragma unroll
        for (int s = 0; s < 4; s++)
#pragma unroll
            for (int e = 0; e < 4; e++) acc[s][e] = 0.0f;

#pragma unroll 8
        for (int kt = 0; kt < 32; kt++) {
            const int rs = kt & 7;
            uint32_t a[4] = {pw[rs].x, pw[rs].y, pw[rs].z, pw[rs].w};
            if (kt + 8 < 32) pw[rs] = wfrag[(kt + 8) * 32];
            const uint32_t blkoff = (uint32_t)((kh * 8 + (kt >> 2)) * 4096);
            const uint32_t cs = (uint32_t)((kt & 3) * 32);
            uint32_t b0[4], b1[4];
            LDSM4(b0, smb + RSM_H + blkoff + SW128(brow0 + cs));
            LDSM4(b1, smb + RSM_H + blkoff + SW128(brow1 + cs));
            MMA_F16(acc[0], a, b0[0], b0[1]);
            MMA_F16(acc[1], a, b0[2], b0[3]);
            MMA_F16(acc[2], a, b1[0], b1[1]);
            MMA_F16(acc[3], a, b1[2], b1[3]);
        }

        // write K-half partial G fragments
        {
            float* Gk = kh ? G1 : G0;
            int r0 = mi * 16 + (lane >> 2);
            int cc = (lane & 3) * 2;
#pragma unroll
            for (int s = 0; s < 4; s++) {
                int col = (s >> 1) * 16 + (s & 1) * 8 + cc;
                Gk[r0 * 33 + col]           = acc[s][0];
                Gk[r0 * 33 + col + 1]       = acc[s][1];
                Gk[(r0 + 8) * 33 + col]     = acc[s][2];
                Gk[(r0 + 8) * 33 + col + 1] = acc[s][3];
            }
        }
        __syncthreads();

        // gate combine + state update + outputs
#pragma unroll
        for (int q = 0; q < 2; q++) {
            int u = uu[q], b = bb[q];
            float iv = hsig (G0[( 0 + u) * 33 + b] + G1[( 0 + u) * 33 + b] + gxbuf[b * 68 + 0 * 16 + u]);
            float fv = hsig (G0[(16 + u) * 33 + b] + G1[(16 + u) * 33 + b] + gxbuf[b * 68 + 1 * 16 + u]);
            float gv = clip1(G0[(32 + u) * 33 + b] + G1[(32 + u) * 33 + b] + gxbuf[b * 68 + 2 * 16 + u]);
            float ov = hsig (G0[(48 + u) * 33 + b] + G1[(48 + u) * 33 + b] + gxbuf[b * 68 + 3 * 16 + u]);
            float c  = fv * cst[q] + iv * gv;
            cst[q]   = c;
            float h  = ov * clip1(c);
            int gk = cb * 16 + u;
            g_hH[dir][par ^ 1][b * 1024 + gk] = __float2half_rn(h);
            if (yfp) yfp[(size_t)te * BATCH * YW + (size_t)b * YW + dir * HID + gk] = h;
            if (yh)  yh[(size_t)(te * BATCH + b) * YW + dir * HID + gk] = __float2half_rn(h);
        }

        if (t < T_STEPS - 1) {
            // prefetch next step's W ring BEFORE the barrier wait
#pragma unroll
            for (int s = 0; s < 8; s++) pw[s] = wfrag[s * 32];
            flag_barrier(dir, cb, (unsigned)(t + 1));
        }
    }

    grid_barrier(dir, sense);   // final: keeps legacy phase parity even per launch
}

// ---------------- launch ----------------
extern "C" void kernel_launch(void* const* d_in, const int* in_sizes, int n_in,
                              void* d_out, int out_size)
{
    (void)in_sizes; (void)n_in; (void)out_size;

    const float* x  = (const float*)d_in[0];
    const float* h0 = (const float*)d_in[1];
    const float* c0 = (const float*)d_in[2];
    const float* P[24];
    for (int i = 0; i < 24; i++) P[i] = (const float*)d_in[3 + i];
    // P[(l*2+d)*4 + {0:w_ih, 1:w_hh, 2:b_ih, 3:b_hh}]

    float* gxp = nullptr;
    __half *wih = nullptr, *act = nullptr;
    uint4* wrec = nullptr;
    cudaGetSymbolAddress((void**)&gxp,  g_gx);
    cudaGetSymbolAddress((void**)&wih,  g_wih);
    cudaGetSymbolAddress((void**)&act,  g_act);
    cudaGetSymbolAddress((void**)&wrec, g_wrec);
    cudaFuncSetAttribute(rec_kernel, cudaFuncAttributeMaxDynamicSharedMemorySize, REC_SMEM);
    cudaFuncSetAttribute(gemm_mma,   cudaFuncAttributeMaxDynamicSharedMemorySize, GEMM_SMEM);

    float* out = (float*)d_out;

    // launch 1: bake W_hh fp16 fragment streams
    W6 w6;
    for (int i = 0; i < 6; i++) w6.w[i] = P[i * 4 + 1];
    wrec_prep<<<dim3(64, 6), 256>>>(w6, wrec);

    // launch 2: convert all 6 w_ih to fp16
    W6 w6i;
    for (int i = 0; i < 6; i++) w6i.w[i] = P[i * 4];
    wih_split<<<dim3(8192, 6), 256>>>(w6i, wih);

    const size_t woff[6] = {0, 1310720, 2621440, 11010048, 19398656, 27787264};
    dim3 gg(GDIM / 128, MROWS / 128, 2), gb(256);

    // layer 0 (K=320, fp32 x converted in staging)
    gemm_mma<<<gg, gb, GEMM_SMEM>>>(320, x, nullptr,
                                    wih + woff[0], wih + woff[1],
                                    P[2], P[3], P[6], P[7], gxp);
    rec_kernel<<<128, 256, REC_SMEM>>>(wrec, h0, c0, 0, gxp, nullptr, act);

    // layer 1 (K=2048, pipelined)
    gemm_mma<<<gg, gb, GEMM_SMEM>>>(2048, nullptr, act,
                                    wih + woff[2], wih + woff[3],
                                    P[10], P[11], P[14], P[15], gxp);
    rec_kernel<<<128, 256, REC_SMEM>>>(wrec, h0, c0, 1, gxp, nullptr, act);

    // layer 2 (K=2048, pipelined) -> fp32 output
    gemm_mma<<<gg, gb, GEMM_SMEM>>>(2048, nullptr, act,
                                    wih + woff[4], wih + woff[5],
                                    P[18], P[19], P[22], P[23], gxp);
    rec_kernel<<<128, 256, REC_SMEM>>>(wrec, h0, c0, 2, gxp, out, nullptr);
}

// round 17
// speedup vs baseline: 1.1520x; 1.1520x over previous
#include <cuda_runtime.h>
#include <cuda_fp16.h>
#include <cstdint>
#include <cstddef>

#define T_STEPS 512
#define BATCH   32
#define HID     1024
#define GDIM    4096
#define MROWS   16384          // T*B
#define YW      2048           // 2*H

typedef unsigned long long ull;

// ---------------- device scratch (no runtime allocation) ----------------
__device__ float g_gx[134217728];          // [2][MROWS][GDIM]  512 MB
__device__ __half g_hH[2][2][32 * 1024];   // [dir][parity][b*1024+k] fp16
__device__ unsigned g_bar_cnt[2]   = {0, 0};
__device__ unsigned g_bar_phase[2] = {0, 0};
__device__ unsigned g_cnt1[2][8];          // hierarchical level-1 counters
__device__ unsigned g_cnt2[2];             // hierarchical level-2 counter
__device__ unsigned g_ph2[2];              // hierarchical phase (step number)
__device__ __half g_wih[36700160];         // w_ih fp16 (all 6)
__device__ __half g_act[33554432];         // activations fp16 [16384 x 2048]
// W_hh baked per-thread fragment streams (8 warps = 4 mi x 2 kh):
// [ld 6][cb 64][wr 8][kt 32][lane 32] x 16B (one fp16 A-fragment)
__device__ uint4 g_wrec[3145728];          // 48 MB

// ---------------- helpers ----------------
__device__ __forceinline__ uint32_t smem_u32(const void* p) {
    uint32_t a;
    asm("{ .reg .u64 t; cvta.to.shared.u64 t, %1; cvt.u32.u64 %0, t; }" : "=r"(a) : "l"(p));
    return a;
}
#define SW128(o) ((o) ^ (((o) >> 3) & 0x70))

#define MMA_F16(d, a, b0v, b1v)                                               \
    asm volatile("mma.sync.aligned.m16n8k16.row.col.f32.f16.f16.f32 "         \
        "{%0,%1,%2,%3}, {%4,%5,%6,%7}, {%8,%9}, {%0,%1,%2,%3};"               \
        : "+f"((d)[0]), "+f"((d)[1]), "+f"((d)[2]), "+f"((d)[3])              \
        : "r"((a)[0]), "r"((a)[1]), "r"((a)[2]), "r"((a)[3]),                 \
          "r"(b0v), "r"(b1v))

#define LDSM4(r, addr)                                                        \
    asm volatile("ldmatrix.sync.aligned.m8n8.x4.shared.b16 "                  \
        "{%0,%1,%2,%3}, [%4];"                                                \
        : "=r"((r)[0]), "=r"((r)[1]), "=r"((r)[2]), "=r"((r)[3])              \
        : "r"(addr))

#define CP_ASYNC16(smaddr, gaddr)                                             \
    asm volatile("cp.async.cg.shared.global [%0], [%1], 16;"                  \
        :: "r"(smaddr), "l"(gaddr) : "memory")
#define CP_COMMIT() asm volatile("cp.async.commit_group;" ::: "memory")
#define CP_WAIT0()  asm volatile("cp.async.wait_group 0;" ::: "memory")
#define CP_WAIT1()  asm volatile("cp.async.wait_group 1;" ::: "memory")

__device__ __forceinline__ float hsig(float v)  { return fminf(fmaxf(fmaf(v, 0.2f, 0.5f), 0.0f), 1.0f); }
__device__ __forceinline__ float clip1(float v) { return fminf(fmaxf(v, -1.0f), 1.0f); }

// legacy counter barrier (used exactly twice per launch: init + final -> even parity)
__device__ __forceinline__ void grid_barrier(int dir, unsigned& sense) {
    __syncthreads();
    sense ^= 1u;
    if (threadIdx.x == 0) {
        unsigned prev;
        asm volatile("atom.add.acq_rel.gpu.u32 %0, [%1], 1;"
                     : "=r"(prev) : "l"(&g_bar_cnt[dir]) : "memory");
        if (prev == 63u) {
            asm volatile("st.relaxed.gpu.u32 [%0], %1;"
                         :: "l"(&g_bar_cnt[dir]), "r"(0u) : "memory");
            unsigned dummy;
            asm volatile("atom.exch.release.gpu.b32 %0, [%1], %2;"
                         : "=r"(dummy) : "l"(&g_bar_phase[dir]), "r"(sense) : "memory");
        } else {
            unsigned ph;
            do {
                __nanosleep(64);
                asm volatile("ld.acquire.gpu.u32 %0, [%1];"
                             : "=r"(ph) : "l"(&g_bar_phase[dir]) : "memory");
            } while (ph != sense);
        }
    }
    __syncthreads();
}

// hierarchical monotonic barrier: 8x8 arrival tree, single-word detection
__device__ __forceinline__ void hier_barrier(int dir, int cb, unsigned t) {
    __syncthreads();
    if (threadIdx.x == 0) {
        const unsigned tgt = t + 1u;
        unsigned prev;
        asm volatile("atom.add.acq_rel.gpu.u32 %0, [%1], 1;"
                     : "=r"(prev) : "l"(&g_cnt1[dir][cb >> 3]) : "memory");
        if (prev == tgt * 8u - 1u) {              // last of my group this step
            unsigned p2;
            asm volatile("atom.add.acq_rel.gpu.u32 %0, [%1], 1;"
                         : "=r"(p2) : "l"(&g_cnt2[dir]) : "memory");
            if (p2 == tgt * 8u - 1u) {            // last group this step
                asm volatile("st.release.gpu.u32 [%0], %1;"
                             :: "l"(&g_ph2[dir]), "r"(tgt) : "memory");
            }
        }
        unsigned ph;
        do {
            asm volatile("ld.acquire.gpu.u32 %0, [%1];"
                         : "=r"(ph) : "l"(&g_ph2[dir]) : "memory");
            if (ph >= tgt) break;
            __nanosleep(32);
        } while (1);
    }
    __syncthreads();
}

// ---------------- W_hh prep: bake fp16 fragment streams ----------------
// Rec warp layout: wr(0..7) -> mi = wr>>1 (gate tile), kh = wr&1 (K half).
struct W6 { const float* w[6]; };

__global__ void __launch_bounds__(256)
wrec_prep(W6 p, uint4* __restrict__ out)
{
    const int cb = blockIdx.x;
    const int ld = blockIdx.y;
    const float* __restrict__ w = p.w[ld];
    for (int it = 0; it < 32; it++) {
        int v    = it * 256 + threadIdx.x;   // 0..8191 = 8 wr x 32 kt x 32 lanes
        int wr   = v >> 10;
        int kt   = (v >> 5) & 31;
        int lane = v & 31;
        int mi = wr >> 1, kh = wr & 1;
        unsigned short fr[8];
#pragma unroll
        for (int j = 0; j < 4; j++) {
            int r  = (lane >> 2) + (j & 1) * 8;
            int kc = (lane & 3) * 2 + (j >> 1) * 8;
            int row = mi * HID + cb * 16 + r;
            int k   = kh * 512 + kt * 16 + kc;
#pragma unroll
            for (int e = 0; e < 2; e++) {
                __half h = __float2half_rn(w[(size_t)row * HID + k + e]);
                fr[j * 2 + e] = *(unsigned short*)&h;
            }
        }
        out[(((size_t)(ld * 64 + cb) * 8 + wr) * 32 + kt) * 32 + lane] = *(uint4*)fr;
    }
}

// ---------------- w_ih fp16 conversion (all 6 in one launch) ----------------
__global__ void __launch_bounds__(256)
wih_split(W6 p, __half* __restrict__ out_base)
{
    const int ld = blockIdx.y;
    const size_t woff = (ld == 0) ? 0u :
                        (ld == 1) ? 1310720u :
                        (size_t)2621440u + (size_t)(ld - 2) * 8388608u;
    const int n4 = (ld < 2) ? 327680 : 2097152;
    int i = blockIdx.x * 256 + threadIdx.x;
    if (i >= n4) return;
    float4 v = ((const float4*)p.w[ld])[i];
    __half2* O = (__half2*)(out_base + woff) + i * 2;
    O[0] = __half2(__float2half_rn(v.x), __float2half_rn(v.y));
    O[1] = __half2(__float2half_rn(v.z), __float2half_rn(v.w));
}

// ---------------- tensor-core input-projection GEMM (fp16, 2-stage cp.async) ----------------
#define SMO_A 0
#define SMO_B 16384
#define STAGE_BYTES 32768
#define SMO_BIAS 65536
#define GEMM_SMEM (65536 + 512)

__global__ void __launch_bounds__(256)
gemm_mma(int K, const float* __restrict__ Afp,
         const __half* __restrict__ Ah,
         const __half* __restrict__ WF, const __half* __restrict__ WR,
         const float* __restrict__ bf1, const float* __restrict__ bf2,
         const float* __restrict__ br1, const float* __restrict__ br2,
         float* __restrict__ G)
{
    extern __shared__ char sm[];
    const uint32_t smb = smem_u32(sm);
    const int tid  = threadIdx.x;
    const int wid  = tid >> 5;
    const int lane = tid & 31;
    const int z    = blockIdx.z;

    const __half* __restrict__ W  = z ? WR  : WF;
    const float* __restrict__ b1 = z ? br1 : bf1;
    const float* __restrict__ b2 = z ? br2 : bf2;
    float* __restrict__ Gz = G + (size_t)z * MROWS * GDIM;

    const int n0 = blockIdx.x * 128;
    const int m0 = blockIdx.y * 128;
    const int wm = (wid >> 2) * 64;
    const int wn = (wid & 3) * 32;

    {
        float* bias = (float*)(sm + SMO_BIAS);
        if (tid < 128) bias[tid] = b1[n0 + tid] + b2[n0 + tid];
    }

    float acc[4][4][4];
#pragma unroll
    for (int mi = 0; mi < 4; mi++)
#pragma unroll
        for (int ni = 0; ni < 4; ni++)
#pragma unroll
            for (int e = 0; e < 4; e++) acc[mi][ni][e] = 0.0f;

    const int nk = K >> 6;

    int srow[4], scol[4];
    uint32_t soff[4];
#pragma unroll
    for (int i = 0; i < 4; i++) {
        int v = tid + i * 256;
        srow[i] = v >> 3;
        scol[i] = (v & 7) * 8;
        soff[i] = SW128((uint32_t)(srow[i] * 128 + (v & 7) * 16));
    }

#define GEMM_MMA_CHUNK(SB)                                                    \
    {                                                                         \
        _Pragma("unroll")                                                     \
        for (int ks = 0; ks < 4; ks++) {                                      \
            uint32_t ah[4][4], bh[2][4];                                      \
            _Pragma("unroll")                                                 \
            for (int mi = 0; mi < 4; mi++) {                                  \
                uint32_t off = SW128((uint32_t)(                              \
                    (wm + mi * 16 + (lane & 15)) * 128 + ks * 32 + (lane >> 4) * 16)); \
                LDSM4(ah[mi], smb + (SB) + SMO_A + off);                      \
            }                                                                 \
            _Pragma("unroll")                                                 \
            for (int p = 0; p < 2; p++) {                                     \
                int q  = lane >> 3;                                           \
                int nf = q >> 1, kl = q & 1;                                  \
                uint32_t off = SW128((uint32_t)(                              \
                    (wn + p * 16 + nf * 8 + (lane & 7)) * 128 + ks * 32 + kl * 16)); \
                LDSM4(bh[p], smb + (SB) + SMO_B + off);                       \
            }                                                                 \
            _Pragma("unroll")                                                 \
            for (int mi = 0; mi < 4; mi++) {                                  \
                _Pragma("unroll")                                             \
                for (int ni = 0; ni < 4; ni++) {                              \
                    const int p = ni >> 1, s = (ni & 1) * 2;                  \
                    MMA_F16(acc[mi][ni], ah[mi], bh[p][s], bh[p][s + 1]);     \
                }                                                             \
            }                                                                 \
        }                                                                     \
    }

    if (Afp) {
        for (int ch = 0; ch < nk; ch++) {
            const int kc = ch * 64;
            __syncthreads();
#pragma unroll
            for (int i = 0; i < 4; i++) {
                size_t ga = (size_t)(m0 + srow[i]) * K + kc + scol[i];
                size_t gb = (size_t)(n0 + srow[i]) * K + kc + scol[i];
                float4 f0 = *(const float4*)(Afp + ga);
                float4 f1 = *(const float4*)(Afp + ga + 4);
                float fv[8] = {f0.x, f0.y, f0.z, f0.w, f1.x, f1.y, f1.z, f1.w};
                unsigned short hh[8];
#pragma unroll
                for (int j = 0; j < 8; j++) {
                    __half h = __float2half_rn(fv[j]);
                    hh[j] = *(unsigned short*)&h;
                }
                *(uint4*)(sm + SMO_A + soff[i]) = *(uint4*)hh;
                *(uint4*)(sm + SMO_B + soff[i]) = *(const uint4*)(W + gb);
            }
            __syncthreads();
            GEMM_MMA_CHUNK(0u)
        }
    } else {
#define GEMM_STAGE(CH, PB)                                                    \
        {                                                                     \
            const int kc_ = (CH) * 64;                                        \
            const uint32_t sb_ = (uint32_t)(PB) * STAGE_BYTES;                \
            _Pragma("unroll")                                                 \
            for (int i = 0; i < 4; i++) {                                     \
                size_t ga = (size_t)(m0 + srow[i]) * K + kc_ + scol[i];       \
                size_t gb = (size_t)(n0 + srow[i]) * K + kc_ + scol[i];       \
                CP_ASYNC16(smb + sb_ + SMO_A + soff[i], Ah + ga);             \
                CP_ASYNC16(smb + sb_ + SMO_B + soff[i], W + gb);              \
            }                                                                 \
        }
        GEMM_STAGE(0, 0)
        CP_COMMIT();
        for (int ch = 0; ch < nk; ch++) {
            if (ch + 1 < nk) {
                GEMM_STAGE(ch + 1, (ch + 1) & 1)
                CP_COMMIT();
                CP_WAIT1();
            } else {
                CP_WAIT0();
            }
            __syncthreads();
            const uint32_t sb = (uint32_t)(ch & 1) * STAGE_BYTES;
            GEMM_MMA_CHUNK(sb)
            __syncthreads();
        }
#undef GEMM_STAGE
    }

    const float* bias = (const float*)(sm + SMO_BIAS);
    const int qr = lane >> 2;
    const int qc = (lane & 3) * 2;
#pragma unroll
    for (int mi = 0; mi < 4; mi++) {
#pragma unroll
        for (int ni = 0; ni < 4; ni++) {
            int col = wn + ni * 8 + qc;
            float bx = bias[col], by = bias[col + 1];
            size_t base0 = (size_t)(m0 + wm + mi * 16 + qr) * GDIM + n0 + col;
            size_t base1 = base0 + (size_t)8 * GDIM;
            *(float2*)&Gz[base0] = make_float2(acc[mi][ni][0] + bx, acc[mi][ni][1] + by);
            *(float2*)&Gz[base1] = make_float2(acc[mi][ni][2] + bx, acc[mi][ni][3] + by);
        }
    }
}

// ---------------- persistent fp16 tensor-core recurrence (hier barrier) ----------------
// 128 CTAs x 256 threads. dir = blockIdx.x>>6; CTA owns 16 units (64 gate rows).
// Warp wrp: mi = wrp>>1 (gate tile), kh = wrp&1 (K half). Warp = m16 x n32 x K512.
// fp16 single plane; W depth-8 register ring; gx staged coalesced into smem.
#define RSM_H  0
#define RSM_G  65536
#define RSM_GX (65536 + 2*64*33*4)              // 82432
#define REC_SMEM (82432 + 32*68*4)              // 91136 B

__global__ void __launch_bounds__(256)
rec_kernel(const uint4* __restrict__ wrec,
           const float* __restrict__ h0, const float* __restrict__ c0,
           int layer, const float* __restrict__ gx,
           float* __restrict__ yfp, __half* __restrict__ yh)
{
    extern __shared__ char sm[];
    const uint32_t smb = smem_u32(sm);
    float* G0 = (float*)(sm + RSM_G);          // [64][33] K-half 0
    float* G1 = G0 + 64 * 33;                  // [64][33] K-half 1
    float* gxbuf = (float*)(sm + RSM_GX);      // [32][68]

    const int tid  = threadIdx.x;
    const int lane = tid & 31;
    const int wrp  = tid >> 5;
    const int mi   = wrp >> 1;
    const int kh   = wrp & 1;
    const int dir  = blockIdx.x >> 6;
    const int cb   = blockIdx.x & 63;
    const int ld   = layer * 2 + dir;
    const float* __restrict__ gxd = gx + (size_t)dir * MROWS * GDIM;
    const uint4* __restrict__ wfrag =
        wrec + ((size_t)(ld * 64 + cb) * 8 + wrp) * 1024 + lane;

    // reset hierarchical barrier state (published by init legacy barrier)
    if (tid == 0) {
        if ((cb & 7) == 0) {
            asm volatile("st.relaxed.gpu.u32 [%0], %1;"
                         :: "l"(&g_cnt1[dir][cb >> 3]), "r"(0u) : "memory");
        }
        if (cb == 0) {
            asm volatile("st.relaxed.gpu.u32 [%0], %1;"
                         :: "l"(&g_cnt2[dir]), "r"(0u) : "memory");
            asm volatile("st.relaxed.gpu.u32 [%0], %1;"
                         :: "l"(&g_ph2[dir]), "r"(0u) : "memory");
        }
    }

    // c-state: 2 (unit,batch) pairs per thread
    float cst[2];
    int uu[2], bb[2];
#pragma unroll
    for (int q = 0; q < 2; q++) {
        int p = q * 256 + tid;
        uu[q] = p >> 5;
        bb[q] = p & 31;
        size_t sidx = (size_t)(2 * layer + dir) * BATCH * HID +
                      (size_t)bb[q] * HID + cb * 16 + uu[q];
        cst[q] = c0[sidx];
        g_hH[dir][0][bb[q] * 1024 + cb * 16 + uu[q]] = __float2half_rn(h0[sidx]);
    }

    // preload W ring (kt=0..7)
    uint4 pw[8];
#pragma unroll
    for (int s = 0; s < 8; s++) pw[s] = wfrag[s * 32];

    unsigned sense = 0;
    grid_barrier(dir, sense);   // publish initial h + barrier-state resets

    // gx staging coords: 2 float4 per thread
    int gxb[2], gxg[2], gxu[2];
#pragma unroll
    for (int j = 0; j < 2; j++) {
        int v4 = tid + j * 256;
        gxb[j] = v4 >> 4;
        gxg[j] = (v4 & 15) >> 2;
        gxu[j] = (v4 & 3) * 4;
    }

    // ldsm B address components (batches 0-15 and 16-31)
    const int qq = lane >> 3, nf = qq >> 1, kl = qq & 1;
    const uint32_t brow0 = (uint32_t)((nf * 8 + (lane & 7)) * 128 + kl * 16);
    const uint32_t brow1 = brow0 + 16 * 128;

    for (int t = 0; t < T_STEPS; t++) {
        const int par = t & 1;
        const int te  = dir ? (T_STEPS - 1 - t) : t;

        // stage gx (coalesced float4) + h (64KB fp16) into smem
        {
            const float* gxs = gxd + (size_t)te * BATCH * GDIM;
#pragma unroll
            for (int j = 0; j < 2; j++) {
                float4 d = *(const float4*)(gxs + (size_t)gxb[j] * GDIM +
                                            gxg[j] * HID + cb * 16 + gxu[j]);
                *(float4*)(gxbuf + gxb[j] * 68 + gxg[j] * 16 + gxu[j]) = d;
            }
            const uint4* hsrc = (const uint4*)&g_hH[dir][par][0];
#pragma unroll
            for (int i = 0; i < 16; i++) {
                int v = tid + i * 256;
                int b = v >> 7;
                int kx = v & 127;
                int blk = kx >> 3, cq = kx & 7;
                uint4 d = __ldcg(hsrc + v);
                *(uint4*)(sm + blk * 4096 + SW128((uint32_t)(b * 128 + cq * 16))) = d;
            }
        }
        __syncthreads();   // h+gx staged; guards G/gx buffer reuse from prev step

        float acc[4][4];
#pragma unroll
        for (int s = 0; s < 4; s++)
#pragma unroll
            for (int e = 0; e < 4; e++) acc[s][e] = 0.0f;

#pragma unroll 8
        for (int kt = 0; kt < 32; kt++) {
            const int rs = kt & 7;
            uint32_t a[4] = {pw[rs].x, pw[rs].y, pw[rs].z, pw[rs].w};
            if (kt + 8 < 32) pw[rs] = wfrag[(kt + 8) * 32];
            const uint32_t blkoff = (uint32_t)((kh * 8 + (kt >> 2)) * 4096);
            const uint32_t cs = (uint32_t)((kt & 3) * 32);
            uint32_t b0[4], b1[4];
            LDSM4(b0, smb + RSM_H + blkoff + SW128(brow0 + cs));
            LDSM4(b1, smb + RSM_H + blkoff + SW128(brow1 + cs));
            MMA_F16(acc[0], a, b0[0], b0[1]);
            MMA_F16(acc[1], a, b0[2], b0[3]);
            MMA_F16(acc[2], a, b1[0], b1[1]);
            MMA_F16(acc[3], a, b1[2], b1[3]);
        }

        // write K-half partial G fragments
        {
            float* Gk = kh ? G1 : G0;
            int r0 = mi * 16 + (lane >> 2);
            int cc = (lane & 3) * 2;
#pragma unroll
            for (int s = 0; s < 4; s++) {
                int col = (s >> 1) * 16 + (s & 1) * 8 + cc;
                Gk[r0 * 33 + col]           = acc[s][0];
                Gk[r0 * 33 + col + 1]       = acc[s][1];
                Gk[(r0 + 8) * 33 + col]     = acc[s][2];
                Gk[(r0 + 8) * 33 + col + 1] = acc[s][3];
            }
        }
        __syncthreads();

        // gate combine + state update + outputs
#pragma unroll
        for (int q = 0; q < 2; q++) {
            int u = uu[q], b = bb[q];
            float iv = hsig (G0[( 0 + u) * 33 + b] + G1[( 0 + u) * 33 + b] + gxbuf[b * 68 + 0 * 16 + u]);
            float fv = hsig (G0[(16 + u) * 33 + b] + G1[(16 + u) * 33 + b] + gxbuf[b * 68 + 1 * 16 + u]);
            float gv = clip1(G0[(32 + u) * 33 + b] + G1[(32 + u) * 33 + b] + gxbuf[b * 68 + 2 * 16 + u]);
            float ov = hsig (G0[(48 + u) * 33 + b] + G1[(48 + u) * 33 + b] + gxbuf[b * 68 + 3 * 16 + u]);
            float c  = fv * cst[q] + iv * gv;
            cst[q]   = c;
            float h  = ov * clip1(c);
            int gk = cb * 16 + u;
            g_hH[dir][par ^ 1][b * 1024 + gk] = __float2half_rn(h);
            if (yfp) yfp[(size_t)te * BATCH * YW + (size_t)b * YW + dir * HID + gk] = h;
            if (yh)  yh[(size_t)(te * BATCH + b) * YW + dir * HID + gk] = __float2half_rn(h);
        }

        if (t < T_STEPS - 1) {
            // prefetch next step's W ring BEFORE the barrier wait
#pragma unroll
            for (int s = 0; s < 8; s++) pw[s] = wfrag[s * 32];
            hier_barrier(dir, cb, (unsigned)t);
        }
    }

    grid_barrier(dir, sense);   // final: even legacy-phase parity per launch
}

// ---------------- launch ----------------
extern "C" void kernel_launch(void* const* d_in, const int* in_sizes, int n_in,
                              void* d_out, int out_size)
{
    (void)in_sizes; (void)n_in; (void)out_size;

    const float* x  = (const float*)d_in[0];
    const float* h0 = (const float*)d_in[1];
    const float* c0 = (const float*)d_in[2];
    const float* P[24];
    for (int i = 0; i < 24; i++) P[i] = (const float*)d_in[3 + i];
    // P[(l*2+d)*4 + {0:w_ih, 1:w_hh, 2:b_ih, 3:b_hh}]

    float* gxp = nullptr;
    __half *wih = nullptr, *act = nullptr;
    uint4* wrec = nullptr;
    cudaGetSymbolAddress((void**)&gxp,  g_gx);
    cudaGetSymbolAddress((void**)&wih,  g_wih);
    cudaGetSymbolAddress((void**)&act,  g_act);
    cudaGetSymbolAddress((void**)&wrec, g_wrec);
    cudaFuncSetAttribute(rec_kernel, cudaFuncAttributeMaxDynamicSharedMemorySize, REC_SMEM);
    cudaFuncSetAttribute(gemm_mma,   cudaFuncAttributeMaxDynamicSharedMemorySize, GEMM_SMEM);

    float* out = (float*)d_out;

    // launch 1: bake W_hh fp16 fragment streams
    W6 w6;
    for (int i = 0; i < 6; i++) w6.w[i] = P[i * 4 + 1];
    wrec_prep<<<dim3(64, 6), 256>>>(w6, wrec);

    // launch 2: convert all 6 w_ih to fp16
    W6 w6i;
    for (int i = 0; i < 6; i++) w6i.w[i] = P[i * 4];
    wih_split<<<dim3(8192, 6), 256>>>(w6i, wih);

    const size_t woff[6] = {0, 1310720, 2621440, 11010048, 19398656, 27787264};
    dim3 gg(GDIM / 128, MROWS / 128, 2), gb(256);

    // layer 0 (K=320, fp32 x converted in staging)
    gemm_mma<<<gg, gb, GEMM_SMEM>>>(320, x, nullptr,
                                    wih + woff[0], wih + woff[1],
                                    P[2], P[3], P[6], P[7], gxp);
    rec_kernel<<<128, 256, REC_SMEM>>>(wrec, h0, c0, 0, gxp, nullptr, act);

    // layer 1 (K=2048, pipelined)
    gemm_mma<<<gg, gb, GEMM_SMEM>>>(2048, nullptr, act,
                                    wih + woff[2], wih + woff[3],
                                    P[10], P[11], P[14], P[15], gxp);
    rec_kernel<<<128, 256, REC_SMEM>>>(wrec, h0, c0, 1, gxp, nullptr, act);

    // layer 2 (K=2048, pipelined) -> fp32 output
    gemm_mma<<<gg, gb, GEMM_SMEM>>>(2048, nullptr, act,
                                    wih + woff[4], wih + woff[5],
                                    P[18], P[19], P[22], P[23], gxp);
    rec_kernel<<<128, 256, REC_SMEM>>>(wrec, h0, c0, 2, gxp, out, nullptr);
}